// round 17
// baseline (speedup 1.0000x reference)
#include <cuda_runtime.h>
#include <cuda_fp16.h>
#include <cuda_bf16.h>

// PoseProjection: fused rigid-transform trilinear resample.
// CROP = (X=96, Y=96, Z=48), B=8, C=32, VOXEL_SIZE=0.0625 (1/v = 16).
// (ix,iy,iz) = T[:3,:3]*(w,h,d) + T[:3,3]*16,  T = inv(current)@historical.
// Output (concat f32): feat[8,32,48,96,96] | sdf | occ | grid[8,48,96,96,3]
//
// Mega-kernel pipeline: each block (one 64-voxel gather tile) first helps
// drain a global transpose-tile queue (feat f32 ch-major -> f16 ch-last +
// sdf/occ interleave) until its batch is ready AND the queue has advanced
// one batch past it, then gathers. Overlaps DRAM-bound transpose with
// L1-bound gather.
// SMEM layout (union, 12544B): transpose ts[32][65] f32 (8320B)  |
//   gather: s_ow[64][4] int4 (4096B) + st[64][33] f32 (8448B) @ +4096.

#define Bn   8
#define Cn   32
#define Dd   48
#define Hh   96
#define Ww   96
#define HW   (Hh * Ww)          // 9216
#define DHW  (Dd * HW)          // 442368
#define FEATN ((size_t)Bn * Cn * DHW)
#define SDFN  ((size_t)Bn * DHW)

#define VPB  64                 // voxels per tile
#define TPB_TILES (DHW / VPB)   // 6912 tiles per batch
#define TOTAL_TILES (TPB_TILES * Bn)

__device__ float  g_M[Bn][12];
__device__ __half g_featT[(size_t)Bn * DHW * Cn];    // [B][DHW][32] fp16
__device__ float2 g_soT[(size_t)Bn * DHW];           // [B][DHW] {sdf, occ}
__device__ int    g_tnext;                           // global transpose queue
__device__ int    g_tdone[Bn];                       // per-batch tiles done

// ---------------------------------------------------------------------------
// Setup: zero pipeline counters + per-batch T = inv(current) @ historical.
// ---------------------------------------------------------------------------
__global__ void setup_kernel(const float* __restrict__ hist,
                             const float* __restrict__ cur) {
    int b = threadIdx.x;
    if (b == 0) g_tnext = 0;
    if (b < Bn) g_tdone[b] = 0;
    if (b >= Bn) return;

    float A[4][4], Inv[4][4];
    for (int i = 0; i < 4; i++)
        for (int j = 0; j < 4; j++) {
            A[i][j]   = cur[b * 16 + i * 4 + j];
            Inv[i][j] = (i == j) ? 1.f : 0.f;
        }
    for (int c = 0; c < 4; c++) {
        int p = c; float mx = fabsf(A[c][c]);
        for (int r = c + 1; r < 4; r++) {
            float v = fabsf(A[r][c]);
            if (v > mx) { mx = v; p = r; }
        }
        if (p != c)
            for (int j = 0; j < 4; j++) {
                float t = A[c][j]; A[c][j] = A[p][j]; A[p][j] = t;
                t = Inv[c][j]; Inv[c][j] = Inv[p][j]; Inv[p][j] = t;
            }
        float f = 1.0f / A[c][c];
        for (int j = 0; j < 4; j++) { A[c][j] *= f; Inv[c][j] *= f; }
        for (int r = 0; r < 4; r++) {
            if (r == c) continue;
            float g = A[r][c];
            for (int j = 0; j < 4; j++) {
                A[r][j]   -= g * A[c][j];
                Inv[r][j] -= g * Inv[c][j];
            }
        }
    }
    for (int i = 0; i < 3; i++)
        for (int j = 0; j < 4; j++) {
            float s = 0.f;
            for (int k = 0; k < 4; k++)
                s += Inv[i][k] * hist[b * 16 + k * 4 + j];
            g_M[b][i * 4 + j] = (j == 3) ? s * 16.0f : s;
        }
}

// ---------------------------------------------------------------------------
// Corner computation.
// ---------------------------------------------------------------------------
__device__ __forceinline__ void corners(const float* __restrict__ M,
                                        int w, int h, int d,
                                        int off[8], float wgt[8],
                                        float& ix, float& iy, float& iz) {
    float fw = (float)w, fh = (float)h, fd = (float)d;
    ix = fmaf(M[0], fw, fmaf(M[1], fh, fmaf(M[2],  fd, M[3])));
    iy = fmaf(M[4], fw, fmaf(M[5], fh, fmaf(M[6],  fd, M[7])));
    iz = fmaf(M[8], fw, fmaf(M[9], fh, fmaf(M[10], fd, M[11])));

    float x0f = floorf(ix), y0f = floorf(iy), z0f = floorf(iz);
    float fx = ix - x0f, fy = iy - y0f, fz = iz - z0f;
    int x0 = (int)x0f, y0 = (int)y0f, z0 = (int)z0f;

    bool vx0 = (x0 >= 0) & (x0 < Ww), vx1 = (x0 + 1 >= 0) & (x0 + 1 < Ww);
    bool vy0 = (y0 >= 0) & (y0 < Hh), vy1 = (y0 + 1 >= 0) & (y0 + 1 < Hh);
    bool vz0 = (z0 >= 0) & (z0 < Dd), vz1 = (z0 + 1 >= 0) & (z0 + 1 < Dd);
    int xc0 = min(max(x0, 0), Ww - 1),     xc1 = min(max(x0 + 1, 0), Ww - 1);
    int yc0 = min(max(y0, 0), Hh - 1),     yc1 = min(max(y0 + 1, 0), Hh - 1);
    int zc0 = min(max(z0, 0), Dd - 1),     zc1 = min(max(z0 + 1, 0), Dd - 1);

    float wx0 = 1.f - fx, wx1 = fx;
    float wy0 = 1.f - fy, wy1 = fy;
    float wz0 = 1.f - fz, wz1 = fz;

    int rb00 = zc0 * HW + yc0 * Ww;
    int rb01 = zc0 * HW + yc1 * Ww;
    int rb10 = zc1 * HW + yc0 * Ww;
    int rb11 = zc1 * HW + yc1 * Ww;

    off[0] = rb00 + xc0; off[1] = rb00 + xc1;
    off[2] = rb01 + xc0; off[3] = rb01 + xc1;
    off[4] = rb10 + xc0; off[5] = rb10 + xc1;
    off[6] = rb11 + xc0; off[7] = rb11 + xc1;

    wgt[0] = (vx0 & vy0 & vz0) ? wx0 * wy0 * wz0 : 0.f;
    wgt[1] = (vx1 & vy0 & vz0) ? wx1 * wy0 * wz0 : 0.f;
    wgt[2] = (vx0 & vy1 & vz0) ? wx0 * wy1 * wz0 : 0.f;
    wgt[3] = (vx1 & vy1 & vz0) ? wx1 * wy1 * wz0 : 0.f;
    wgt[4] = (vx0 & vy0 & vz1) ? wx0 * wy0 * wz1 : 0.f;
    wgt[5] = (vx1 & vy0 & vz1) ? wx1 * wy0 * wz1 : 0.f;
    wgt[6] = (vx0 & vy1 & vz1) ? wx0 * wy1 * wz1 : 0.f;
    wgt[7] = (vx1 & vy1 & vz1) ? wx1 * wy1 * wz1 : 0.f;
}

// ---------------------------------------------------------------------------
// Mega kernel: help-transpose loop, then gather own tile.
// ---------------------------------------------------------------------------
__global__ void __launch_bounds__(256)
mega_kernel(const float* __restrict__ feat,
            const float* __restrict__ sdf,
            const float* __restrict__ occ,
            float* __restrict__ out) {
    // smem union (12544B): ts[32][65] f32 | s_ow[64][4] int4 + st[64][33] f32
    __shared__ __align__(16) char smraw[12544];
    float (*ts)[65]   = (float(*)[65])smraw;                // 8320B
    int4  (*s_ow)[4]  = (int4(*)[4])smraw;                  // 4096B
    float (*st)[33]   = (float(*)[33])(smraw + 4096);       // 8448B
    __shared__ int s_t;

    int tid = threadIdx.x;
    int bid = blockIdx.x;
    int myb    = bid / TPB_TILES;
    int mytile = bid - myb * TPB_TILES;
    int helpLimit = (myb >= Bn - 2) ? TOTAL_TILES : (myb + 2) * TPB_TILES;

    // ---- phase A: help drain the transpose queue ----
    for (;;) {
        __syncthreads();
        if (tid == 0) {
            int done = *(volatile int*)&g_tdone[myb];
            int nxt  = *(volatile int*)&g_tnext;
            int t = -1;                              // -1: ready -> gather
            if (!(done == TPB_TILES && nxt >= helpLimit)) {
                t = atomicAdd(&g_tnext, 1);
                if (t >= TOTAL_TILES) t = -2;        // -2: drained, wait
            }
            s_t = t;
        }
        __syncthreads();
        int t = s_t;
        if (t == -1) break;
        if (t == -2) {
            if (tid == 0)
                while (*(volatile int*)&g_tdone[myb] != TPB_TILES)
                    __nanosleep(128);
            __syncthreads();
            break;
        }

        // transpose tile t: batch tb, voxels [n0, n0+64)
        int tb = t / TPB_TILES;
        int n0 = (t - tb * TPB_TILES) * VPB;
        {
            int r = tid >> 3;           // channel 0..31
            int q = tid & 7;            // 0..7
            const float* fp = feat + (size_t)tb * Cn * DHW + (size_t)r * DHW + n0 + q * 8;
            float4 v0 = *(const float4*)(fp);
            float4 v1 = *(const float4*)(fp + 4);
            ts[r][q * 8 + 0] = v0.x; ts[r][q * 8 + 1] = v0.y;
            ts[r][q * 8 + 2] = v0.z; ts[r][q * 8 + 3] = v0.w;
            ts[r][q * 8 + 4] = v1.x; ts[r][q * 8 + 5] = v1.y;
            ts[r][q * 8 + 6] = v1.z; ts[r][q * 8 + 7] = v1.w;
        }
        if (tid < VPB) {
            size_t idx = (size_t)tb * DHW + n0 + tid;
            g_soT[idx] = make_float2(sdf[idx], occ[idx]);
        }
        __syncthreads();
        {
            int vox  = tid >> 2;        // 0..63
            int part = tid & 3;         // 0..3
            int c0 = part * 8;
            __half2 h[4];
            #pragma unroll
            for (int i = 0; i < 4; i++)
                h[i] = __floats2half2_rn(ts[c0 + 2 * i][vox], ts[c0 + 2 * i + 1][vox]);
            uint4 u = make_uint4(*(unsigned*)&h[0], *(unsigned*)&h[1],
                                 *(unsigned*)&h[2], *(unsigned*)&h[3]);
            char* dst = (char*)g_featT + ((size_t)tb * DHW + n0 + vox) * (Cn * 2) + part * 16;
            *(uint4*)dst = u;
        }
        __threadfence();                 // release: make tile visible
        __syncthreads();                 // all threads fenced before count
        if (tid == 0) atomicAdd(&g_tdone[tb], 1);
    }
    __threadfence();                     // acquire side
    __syncthreads();                     // smem union handoff ts -> s_ow/st

    // ---- phase B: gather my tile ----
    int b  = myb;
    int n0 = mytile * VPB;

    if (tid < VPB) {
        int n = n0 + tid;
        int w = n % Ww;
        int h = (n / Ww) % Hh;
        int d = n / HW;
        int off[8]; float wgt[8]; float ix, iy, iz;
        corners(g_M[b], w, h, d, off, wgt, ix, iy, iz);
        #pragma unroll
        for (int j = 0; j < 4; j++)
            s_ow[tid][j] = make_int4(off[2 * j], off[2 * j + 1],
                                     __float_as_int(wgt[2 * j]),
                                     __float_as_int(wgt[2 * j + 1]));

        // sdf/occ gather (registers)
        const float2* so = g_soT + (size_t)b * DHW;
        float as = 0.f, ao = 0.f;
        #pragma unroll
        for (int k = 0; k < 8; k++) {
            float2 v = __ldg(so + off[k]);
            as = fmaf(wgt[k], v.x, as);
            ao = fmaf(wgt[k], v.y, ao);
        }
        out[FEATN + (size_t)b * DHW + n]        = as;
        out[FEATN + SDFN + (size_t)b * DHW + n] = ao;

        // grid output [B,D,H,W,3]
        float* g = out + FEATN + 2 * SDFN + ((size_t)b * DHW + n) * 3;
        g[0] = 2.0f * ix * (1.0f / 95.0f) - 1.0f;
        g[1] = 2.0f * iy * (1.0f / 95.0f) - 1.0f;
        g[2] = 2.0f * iz * (1.0f / 47.0f) - 1.0f;
    }
    __syncthreads();

    const char* fT = (const char*)g_featT + (size_t)b * DHW * (Cn * 2);
    #pragma unroll
    for (int r = 0; r < VPB * 8 / 256; r++) {       // 2 rounds
        int task = r * 256 + tid;
        int vl  = task >> 3;        // voxel 0..63
        int ch4 = task & 7;         // channel group 0..7

        float a0 = 0.f, a1 = 0.f, a2 = 0.f, a3 = 0.f;
        #pragma unroll
        for (int j = 0; j < 4; j++) {
            int4 ow = s_ow[vl][j];
            {   // even corner
                uint2 u = __ldg((const uint2*)(fT + (size_t)ow.x * (Cn * 2) + ch4 * 8));
                float wk = __int_as_float(ow.z);
                float2 f0 = __half22float2(*(const __half2*)&u.x);
                float2 f1 = __half22float2(*(const __half2*)&u.y);
                a0 = fmaf(wk, f0.x, a0); a1 = fmaf(wk, f0.y, a1);
                a2 = fmaf(wk, f1.x, a2); a3 = fmaf(wk, f1.y, a3);
            }
            {   // odd corner
                uint2 u = __ldg((const uint2*)(fT + (size_t)ow.y * (Cn * 2) + ch4 * 8));
                float wk = __int_as_float(ow.w);
                float2 f0 = __half22float2(*(const __half2*)&u.x);
                float2 f1 = __half22float2(*(const __half2*)&u.y);
                a0 = fmaf(wk, f0.x, a0); a1 = fmaf(wk, f0.y, a1);
                a2 = fmaf(wk, f1.x, a2); a3 = fmaf(wk, f1.y, a3);
            }
        }
        int cb = ch4 * 4;
        st[vl][cb + 0] = a0;
        st[vl][cb + 1] = a1;
        st[vl][cb + 2] = a2;
        st[vl][cb + 3] = a3;
    }
    __syncthreads();

    // coalesced channel-major stores: 64 voxels x 32 ch = 2048 floats
    float* ob = out + (size_t)b * Cn * DHW + n0;
    #pragma unroll
    for (int i = 0; i < VPB * Cn / 256; i++) {      // 8 rounds
        int idx = i * 256 + tid;
        int nl = idx & (VPB - 1);
        int c  = idx >> 6;
        ob[(size_t)c * DHW + nl] = st[nl][c];
    }
}

extern "C" void kernel_launch(void* const* d_in, const int* in_sizes, int n_in,
                              void* d_out, int out_size) {
    const float* feat = (const float*)d_in[0];
    const float* sdf  = (const float*)d_in[1];
    const float* occ  = (const float*)d_in[2];
    const float* hist = (const float*)d_in[3];
    const float* cur  = (const float*)d_in[4];
    float* out = (float*)d_out;

    setup_kernel<<<1, Bn>>>(hist, cur);
    mega_kernel<<<TOTAL_TILES, 256>>>(feat, sdf, occ, out);
}